// round 16
// baseline (speedup 1.0000x reference)
#include <cuda_runtime.h>
#include <cuda_fp16.h>
#include <cstdint>

// Problem constants
#define BS        8
#define RDIM      256
#define NBLK      (BS * RDIM)      // 2048
#define NODES     64
#define MROWS     (NBLK * NODES)   // 131072
#define ENC       31
#define FIN       32
#define HEADS     8
#define HID       64
#define OUTC      32
#define HC12      (HEADS * HID)    // 512
#define HC3       (HEADS * OUTC)   // 256
#define NEG_SLOPE 0.2f

__device__ __forceinline__ uint32_t smem_u32(const void* p) {
    uint32_t a;
    asm("{ .reg .u64 t; cvta.to.shared.u64 t, %1; cvt.u32.u64 %0, t; }" : "=r"(a) : "l"(p));
    return a;
}

// ---------------- mma.sync / ldmatrix / cp.async ----------------
__device__ __forceinline__ void ldsm4(uint32_t* r, uint32_t addr) {
    asm volatile("ldmatrix.sync.aligned.m8n8.x4.shared.b16 {%0,%1,%2,%3}, [%4];"
        : "=r"(r[0]), "=r"(r[1]), "=r"(r[2]), "=r"(r[3]) : "r"(addr));
}
__device__ __forceinline__ void ldsm4t(uint32_t* r, uint32_t addr) {
    asm volatile("ldmatrix.sync.aligned.m8n8.x4.trans.shared.b16 {%0,%1,%2,%3}, [%4];"
        : "=r"(r[0]), "=r"(r[1]), "=r"(r[2]), "=r"(r[3]) : "r"(addr));
}
__device__ __forceinline__ void mma16816(float* d, const uint32_t* a, const uint32_t* b) {
    asm volatile(
        "mma.sync.aligned.m16n8k16.row.col.f32.f16.f16.f32 "
        "{%0,%1,%2,%3}, {%4,%5,%6,%7}, {%8,%9}, {%0,%1,%2,%3};"
        : "+f"(d[0]), "+f"(d[1]), "+f"(d[2]), "+f"(d[3])
        : "r"(a[0]), "r"(a[1]), "r"(a[2]), "r"(a[3]), "r"(b[0]), "r"(b[1]));
}
__device__ __forceinline__ void cp16(uint32_t dst, const void* src) {
    asm volatile("cp.async.cg.shared.global [%0], [%1], 16;" :: "r"(dst), "l"(src));
}
#define CP_COMMIT() asm volatile("cp.async.commit_group;" ::: "memory")
#define CP_WAIT(n)  asm volatile("cp.async.wait_group %0;" :: "n"(n) : "memory")

// ---------------- device scratch ----------------
__device__ __half g_a0[(size_t)MROWS * 64];
__device__ __half g_a1[(size_t)MROWS * HC12];
__device__ __half g_a2[(size_t)MROWS * HC12];
__device__ __half g_w1[512 * 64];
__device__ __half g_w2[512 * 512];
__device__ __half g_w3[256 * 512];

// ---------------- prep kernels ----------------
__global__ void build_x0_h(const float* __restrict__ xs,
                           const float* __restrict__ pos_enc,
                           __half* __restrict__ a0) {
    int idx = blockIdx.x * blockDim.x + threadIdx.x;   // MROWS*64
    if (idx >= MROWS * 64) return;
    int m = idx >> 6;
    int f = idx & 63;
    float v = 0.f;
    if (f == 0) v = xs[m];
    else if (f < FIN) {
        int b = m / (RDIM * NODES);
        int n = m % NODES;
        v = pos_enc[(b * NODES + n) * ENC + (f - 1)];
    }
    a0[idx] = __float2half(v);
}

// All three weight transposes in one launch.
// w1: N=512,Kpad=64,Ksrc=32 (32768) | w2: 512,512,512 (262144) | w3: 256,512,512 (131072)
__global__ void prep_w_all(const float* __restrict__ W1f,
                           const float* __restrict__ W2f,
                           const float* __restrict__ W3f,
                           __half* __restrict__ w1, __half* __restrict__ w2,
                           __half* __restrict__ w3) {
    int idx = blockIdx.x * blockDim.x + threadIdx.x;
    if (idx < 32768) {
        int n = idx >> 6, k = idx & 63;
        float v = (k < FIN) ? W1f[(size_t)k * 512 + n] : 0.f;
        w1[idx] = __float2half(v);
    } else if (idx < 32768 + 262144) {
        int j = idx - 32768;
        int n = j >> 9, k = j & 511;
        w2[j] = __float2half(W2f[(size_t)k * 512 + n]);
    } else if (idx < 32768 + 262144 + 131072) {
        int j = idx - 32768 - 262144;
        int n = j >> 9, k = j & 511;
        w3[j] = __float2half(W3f[(size_t)k * 256 + n]);
    }
}

#define STS_OFF(row, c) ((row) * 64 + ((((c) ^ (((row) >> 1) & 3))) << 4))

// =====================================================================
// WIDE kernel (layers 1-2): tile 128 rows x 128 cols (2 blocks x 2 heads).
// 3-stage cp.async; H fp16 ALIASES the stage region (dead after mainloop);
// ls/ld from accumulators; P hi-only fp16; TC AV; staged store.
// smem: [0,49152) stages / H fp16 [128][136] (alias)
//       [49152, 86016) P hi fp16 [4][64][72]
//       [86016, ...)   sLS/sLD [4][64], sAS/sAD/sBI [128]
// =====================================================================
#define WSTAGE 16384   // A 8KB @0 | B 8KB @8192

template<int K>
__global__ __launch_bounds__(256, 2) void gemm_attn_wide(
    const __half* __restrict__ A, const __half* __restrict__ B,
    const float* __restrict__ a_src, const float* __restrict__ a_dst,
    const float* __restrict__ bias, __half* __restrict__ oact) {
    constexpr int T = K / 32;
    constexpr int OFF_SH   = 0;                  // aliases stage region (49152)
    constexpr int OFF_PH   = 49152;              // P hi fp16 [4][64][72] = 36864
    constexpr int OFF_TAIL = 86016;

    extern __shared__ __align__(16) char smem[];
    float* sLS = (float*)(smem + OFF_TAIL);      // [4][64]
    float* sLD = sLS + 256;                      // [4][64]
    float* sAS = sLD + 256;                      // [128]
    float* sAD = sAS + 128;
    float* sBI = sAD + 128;
    __half* sH = (__half*)(smem + OFF_SH);
    __half* Ph = (__half*)(smem + OFF_PH);

    const int tid  = threadIdx.x;
    const int wid  = tid >> 5;
    const int lane = tid & 31;
    const int gid  = lane >> 2;
    const int tig  = lane & 3;
    const int row0 = blockIdx.y * 128;
    const int col0 = blockIdx.x * 128;
    const uint32_t smem_base = smem_u32(smem);

    // preload attention params; zero ls/ld reducers
    if (tid < 128) {
        sAS[tid] = a_src[col0 + tid];
        sAD[tid] = a_dst[col0 + tid];
        sBI[tid] = bias[col0 + tid];
    }
    sLS[tid] = 0.f;
    sLD[tid] = 0.f;

    // ---- GEMM global->smem mapping ----
    const int arow = tid >> 1;                   // 0..127
    const int ac2  = (tid & 1) * 2;              // chunk 0/2
    const uint32_t sA0 = STS_OFF(arow, ac2);
    const uint32_t sA1 = STS_OFF(arow, ac2 + 1);
    const __half* gA = A + (size_t)(row0 + arow) * K + ac2 * 8;
    const __half* gB = B + (size_t)(col0 + arow) * K + ac2 * 8;

    const int mr = (wid & 1) * 64;               // warp rows (4 m-tiles)
    const int nb = (wid >> 1) * 32;              // warp cols (4 n8-tiles)
    const int rowlA = (lane & 7) + ((lane >> 3) & 1) * 8;
    const int chA   = lane >> 4;
    const int rowlB = (lane & 7) + (lane >> 4) * 8;
    const int chB   = (lane >> 3) & 1;

    float acc[4][4][4];
    #pragma unroll
    for (int i = 0; i < 4; i++)
        #pragma unroll
        for (int j = 0; j < 4; j++)
            #pragma unroll
            for (int q = 0; q < 4; q++) acc[i][j][q] = 0.f;

    auto issue = [&](int s, int k0) {
        const uint32_t sb = smem_base + s * WSTAGE;
        cp16(sb + sA0, gA + k0);
        cp16(sb + sA1, gA + k0 + 8);
        cp16(sb + 8192 + sA0, gB + k0);
        cp16(sb + 8192 + sA1, gB + k0 + 8);
    };

    // 3-stage prologue
    issue(0, 0);
    CP_COMMIT();
    if (T > 1) { issue(1, 32); CP_COMMIT(); }

    int buf = 0;
    #pragma unroll 1
    for (int t = 0; t < T; t++) {
        if (t + 1 < T) { CP_WAIT(1); } else { CP_WAIT(0); }
        __syncthreads();
        if (t + 2 < T) {
            int nx = buf + 2; if (nx >= 3) nx -= 3;
            issue(nx, (t + 2) * 32);             // overlaps compute below
            CP_COMMIT();
        }
        const uint32_t stg = smem_base + buf * WSTAGE;
        #pragma unroll
        for (int kk = 0; kk < 2; kk++) {
            const int c0 = kk * 2;
            uint32_t fA[4][4], fB[2][4];
            #pragma unroll
            for (int mt = 0; mt < 4; mt++) {
                int r = mr + mt * 16 + rowlA;
                uint32_t off = r * 64 + (((c0 + chA) ^ ((r >> 1) & 3)) << 4);
                ldsm4(fA[mt], stg + off);
            }
            #pragma unroll
            for (int tp = 0; tp < 2; tp++) {
                int r = nb + tp * 16 + rowlB;
                uint32_t off = r * 64 + (((c0 + chB) ^ ((r >> 1) & 3)) << 4);
                ldsm4(fB[tp], stg + 8192 + off);
            }
            #pragma unroll
            for (int mt = 0; mt < 4; mt++)
                #pragma unroll
                for (int tn = 0; tn < 4; tn++) {
                    const int tp = tn >> 1, hf = (tn & 1) * 2;
                    const uint32_t bb[2] = {fB[tp][hf], fB[tp][hf + 1]};
                    mma16816(acc[mt][tn], fA[mt], bb);
                }
        }
        if (++buf == 3) buf = 0;
    }
    __syncthreads();   // all stage reads done — safe to overwrite with sH

    // ---- epilogue: acc -> sH fp16 (aliased); ls/ld partials from acc ----
    {
        #pragma unroll
        for (int mt = 0; mt < 4; mt++)
            #pragma unroll
            for (int tn = 0; tn < 4; tn++) {
                int r = mr + mt * 16 + gid;
                int c = nb + tn * 8 + tig * 2;
                *(__half2*)&sH[r * 136 + c] =
                    __floats2half2_rn(acc[mt][tn][0], acc[mt][tn][1]);
                *(__half2*)&sH[(r + 8) * 136 + c] =
                    __floats2half2_rn(acc[mt][tn][2], acc[mt][tn][3]);
            }

        float lsp[8], ldp[8];
        #pragma unroll
        for (int i = 0; i < 8; i++) { lsp[i] = 0.f; ldp[i] = 0.f; }
        #pragma unroll
        for (int mt = 0; mt < 4; mt++)
            #pragma unroll
            for (int h = 0; h < 2; h++) {
                const int i = mt * 2 + h;
                #pragma unroll
                for (int tn = 0; tn < 4; tn++)
                    #pragma unroll
                    for (int e = 0; e < 2; e++) {
                        int c = nb + tn * 8 + tig * 2 + e;
                        float a = acc[mt][tn][h * 2 + e];
                        lsp[i] += a * sAS[c];
                        ldp[i] += a * sAD[c];
                    }
            }
        #pragma unroll
        for (int i = 0; i < 8; i++) {
            lsp[i] += __shfl_down_sync(0xffffffffu, lsp[i], 2, 4);
            lsp[i] += __shfl_down_sync(0xffffffffu, lsp[i], 1, 4);
            ldp[i] += __shfl_down_sync(0xffffffffu, ldp[i], 2, 4);
            ldp[i] += __shfl_down_sync(0xffffffffu, ldp[i], 1, 4);
        }
        if (tig == 0) {
            #pragma unroll
            for (int i = 0; i < 8; i++) {
                int ar = mr + (i >> 1) * 16 + gid + (i & 1) * 8;
                int u  = ((ar >> 6) << 1) + (nb >> 6);
                atomicAdd(&sLS[u * 64 + (ar & 63)], lsp[i]);
                atomicAdd(&sLD[u * 64 + (ar & 63)], ldp[i]);
            }
        }
    }
    __syncthreads();

    // ---- softmax: U=4 units, 2 warps each; hi-only fp16 P ----
    {
        const int u  = tid >> 6;
        const int ut = tid & 63;
        const int lw = ut >> 5;
        const float ls0 = sLS[u * 64 + lane];
        const float ls1 = sLS[u * 64 + lane + 32];
        float mxls = fmaxf(ls0, ls1);
        #pragma unroll
        for (int o = 16; o > 0; o >>= 1)
            mxls = fmaxf(mxls, __shfl_xor_sync(0xffffffffu, mxls, o));

        #pragma unroll
        for (int base = 0; base < 32; base += 8) {
            float e0[8], e1[8], s[8];
            #pragma unroll
            for (int r = 0; r < 8; r++) {
                const int i = lw + (base + r) * 2;
                const float ldi = sLD[u * 64 + i];
                float v0 = ldi + ls0;
                float v1 = ldi + ls1;
                v0 = (v0 > 0.f) ? v0 : NEG_SLOPE * v0;
                v1 = (v1 > 0.f) ? v1 : NEG_SLOPE * v1;
                float mr2 = ldi + mxls;        // exact row max (lrelu monotone)
                mr2 = (mr2 > 0.f) ? mr2 : NEG_SLOPE * mr2;
                e0[r] = __expf(v0 - mr2);
                e1[r] = __expf(v1 - mr2);
                s[r] = e0[r] + e1[r];
            }
            #pragma unroll
            for (int o = 16; o > 0; o >>= 1)
                #pragma unroll
                for (int r = 0; r < 8; r++)
                    s[r] += __shfl_xor_sync(0xffffffffu, s[r], o);
            #pragma unroll
            for (int r = 0; r < 8; r++) {
                const int i = lw + (base + r) * 2;
                const float inv = 1.f / s[r];
                Ph[(u * 64 + i) * 72 + lane]      = __float2half(e0[r] * inv);
                Ph[(u * 64 + i) * 72 + lane + 32] = __float2half(e1[r] * inv);
            }
        }
    }
    __syncthreads();

    // ---- AV via tensor cores: per unit out[64x64] = P @ H_unit ----
    {
        const int uu  = wid >> 1;            // unit 0..3
        const int uw  = wid & 1;             // warp within unit
        const int sbu = uu >> 1;             // block half
        const int cb  = (uu & 1) * 64;       // head col offset
        const int m0  = uw * 32;
        const uint32_t Ph_a = smem_base + OFF_PH + uu * 9216;
        const uint32_t sH_a = smem_base + OFF_SH;

        float oa[2][8][4];
        #pragma unroll
        for (int mt = 0; mt < 2; mt++)
            #pragma unroll
            for (int nt = 0; nt < 8; nt++)
                #pragma unroll
                for (int q = 0; q < 4; q++) oa[mt][nt][q] = 0.f;

        #pragma unroll
        for (int kt = 0; kt < 4; kt++) {
            uint32_t ah[2][4];
            #pragma unroll
            for (int mt = 0; mt < 2; mt++)
                ldsm4(ah[mt], Ph_a +
                    (uint32_t)(((m0 + mt * 16 + rowlA) * 72 + kt * 16 + chA * 8) << 1));
            uint32_t fb[4][4];
            #pragma unroll
            for (int ng = 0; ng < 4; ng++) {
                int br = sbu * 64 + kt * 16 + rowlA;
                int bc = cb + ng * 16 + chA * 8;
                ldsm4t(fb[ng], sH_a + (uint32_t)((br * 136 + bc) << 1));
            }
            #pragma unroll
            for (int mt = 0; mt < 2; mt++)
                #pragma unroll
                for (int nt = 0; nt < 8; nt++) {
                    const int ng = nt >> 1, hf = (nt & 1) * 2;
                    const uint32_t bb[2] = {fb[ng][hf], fb[ng][hf + 1]};
                    mma16816(oa[mt][nt], ah[mt], bb);
                }
        }
        __syncthreads();                     // all P/H reads done before overwrite

        // fragments + bias -> sH fp16 (overwrite)
        #pragma unroll
        for (int mt = 0; mt < 2; mt++)
            #pragma unroll
            for (int nt = 0; nt < 8; nt++) {
                int r = sbu * 64 + m0 + mt * 16 + gid;
                int c = cb + nt * 8 + tig * 2;
                float b0f = sBI[c], b1f = sBI[c + 1];
                *(__half2*)&sH[r * 136 + c] =
                    __floats2half2_rn(oa[mt][nt][0] + b0f, oa[mt][nt][1] + b1f);
                *(__half2*)&sH[(r + 8) * 136 + c] =
                    __floats2half2_rn(oa[mt][nt][2] + b0f, oa[mt][nt][3] + b1f);
            }
    }
    __syncthreads();

    // ---- coalesced global store: 2 threads/row, 64 cols each ----
    {
        const int rr = tid >> 1;
        const int hh = tid & 1;
        const uint4* src = (const uint4*)(sH + rr * 136 + hh * 64);
        __half* dst = oact + (size_t)(row0 + rr) * HC12 + col0 + hh * 64;
        #pragma unroll
        for (int k = 0; k < 8; k++)
            *(uint4*)(dst + k * 8) = src[k];
    }
}

// =====================================================================
// Layer-3 kernel: unchanged proven path (tile 128x64, TC AV, mean).
// =====================================================================
#define STAGE 12288

template<int K, int CH>
__global__ __launch_bounds__(256, 2) void gemm_attn_l3(
    const __half* __restrict__ A, const __half* __restrict__ B,
    const float* __restrict__ a_src, const float* __restrict__ a_dst,
    const float* __restrict__ bias, float* __restrict__ outmean) {
    constexpr int HPT = 64 / CH;     // 2
    constexpr int U   = 2 * HPT;     // 4
    constexpr int TU  = 256 / U;     // 64
    constexpr int T   = K / 32;
    constexpr int OFF_SH   = 36864;
    constexpr int OFF_PH   = OFF_SH + 18432;
    constexpr int OFF_TAIL = 92160;

    extern __shared__ __align__(16) char smem[];
    float* sC  = (float*)smem;                   // [128][68] fp32 (aliases stages)
    float* sLS = (float*)(smem + OFF_TAIL);
    float* sLD = sLS + U * 64;
    float* sAS = sLD + U * 64;
    float* sAD = sAS + 64;
    float* sBI = sAD + 64;

    const int tid  = threadIdx.x;
    const int wid  = tid >> 5;
    const int lane = tid & 31;
    const int row0 = blockIdx.y * 128;
    const int col0 = blockIdx.x * 64;
    const uint32_t smem_base = smem_u32(smem);

    const int arow0 = tid >> 2;
    const int ac    = tid & 3;
    const uint32_t a_sts0 = STS_OFF(arow0, ac);
    const uint32_t a_sts1 = STS_OFF(arow0 + 64, ac);
    const uint32_t b_sts  = STS_OFF(arow0, ac);

    const __half* gA0 = A + (size_t)(row0 + arow0) * K + ac * 8;
    const __half* gA1 = gA0 + (size_t)64 * K;
    const __half* gB  = B + (size_t)(col0 + arow0) * K + ac * 8;

    const int mr = (wid & 3) * 32;
    const int nb = (wid >> 2) * 32;
    const int rowlA = (lane & 7) + ((lane >> 3) & 1) * 8;
    const int chA   = (lane >> 4);
    const int rowlB = (lane & 7) + (lane >> 4) * 8;
    const int chB   = (lane >> 3) & 1;

    float acc[2][4][4];
    #pragma unroll
    for (int i = 0; i < 2; i++)
        #pragma unroll
        for (int j = 0; j < 4; j++)
            #pragma unroll
            for (int q = 0; q < 4; q++) acc[i][j][q] = 0.f;

    auto issue_stage = [&](int s, int k0) {
        const uint32_t sb = smem_base + s * STAGE;
        cp16(sb + a_sts0, gA0 + k0);
        cp16(sb + a_sts1, gA1 + k0);
        cp16(sb + 8192 + b_sts, gB + k0);
    };

    issue_stage(0, 0);
    CP_COMMIT();
    if (T > 1) { issue_stage(1, 32); CP_COMMIT(); }

    int buf = 0;
    #pragma unroll 1
    for (int t = 0; t < T; t++) {
        if (t + 1 < T) { CP_WAIT(1); } else { CP_WAIT(0); }
        __syncthreads();
        if (t + 2 < T) {
            int nb3 = buf + 2; if (nb3 >= 3) nb3 -= 3;
            issue_stage(nb3, (t + 2) * 32);
            CP_COMMIT();
        }
        const uint32_t stg = smem_base + buf * STAGE;
        #pragma unroll
        for (int kk = 0; kk < 2; kk++) {
            const int c0 = kk * 2;
            uint32_t fA[2][4], fB[2][4];
            #pragma unroll
            for (int sm = 0; sm < 2; sm++) {
                int r = mr + sm * 16 + rowlA;
                uint32_t off = r * 64 + (((c0 + chA) ^ ((r >> 1) & 3)) << 4);
                ldsm4(fA[sm], stg + off);
            }
            #pragma unroll
            for (int tp = 0; tp < 2; tp++) {
                int r = nb + tp * 16 + rowlB;
                uint32_t off = r * 64 + (((c0 + chB) ^ ((r >> 1) & 3)) << 4);
                ldsm4(fB[tp], stg + 8192 + off);
            }
            #pragma unroll
            for (int sm = 0; sm < 2; sm++)
                #pragma unroll
                for (int tn = 0; tn < 4; tn++) {
                    const int tp = tn >> 1, hf = (tn & 1) * 2;
                    const uint32_t bb[2] = {fB[tp][hf], fB[tp][hf + 1]};
                    mma16816(acc[sm][tn], fA[sm], bb);
                }
        }
        if (++buf == 3) buf = 0;
    }
    __syncthreads();

    {
        const int gid = lane >> 2;
        const int tig = lane & 3;
        __half* sH = (__half*)(smem + OFF_SH);
        #pragma unroll
        for (int sm = 0; sm < 2; sm++) {
            #pragma unroll
            for (int tn = 0; tn < 4; tn++) {
                int r = mr + sm * 16 + gid;
                int c = nb + tn * 8 + tig * 2;
                *(float2*)&sC[r * 68 + c] = make_float2(acc[sm][tn][0], acc[sm][tn][1]);
                *(float2*)&sC[(r + 8) * 68 + c] = make_float2(acc[sm][tn][2], acc[sm][tn][3]);
                *(__half2*)&sH[r * 72 + c] =
                    __floats2half2_rn(acc[sm][tn][0], acc[sm][tn][1]);
                *(__half2*)&sH[(r + 8) * 72 + c] =
                    __floats2half2_rn(acc[sm][tn][2], acc[sm][tn][3]);
            }
        }
    }
    if (tid < 64) {
        sAS[tid] = a_src[col0 + tid];
        sAD[tid] = a_dst[col0 + tid];
        sBI[tid] = bias[col0 + tid];
    }
    __syncthreads();

    const int u  = tid / TU;
    const int ut = tid % TU;
    const int sbu = u / HPT;
    const int hl  = u % HPT;
    const int cb  = hl * CH;

    if (ut < 64) {
        const int n = ut;
        const float* hp = &sC[(sbu * 64 + n) * 68 + cb];
        float ls = 0.f, ld = 0.f;
        #pragma unroll
        for (int c = 0; c < CH; c++) {
            float hv = hp[c];
            ls += hv * sAS[cb + c];
            ld += hv * sAD[cb + c];
        }
        sLS[u * 64 + n] = ls;
        sLD[u * 64 + n] = ld;
    }
    __syncthreads();

    {
        constexpr int NWU   = TU / 32;
        constexpr int NROWS = 64 / NWU;
        const int lw = ut >> 5;
        const float ls0 = sLS[u * 64 + lane];
        const float ls1 = sLS[u * 64 + lane + 32];
        __half* sPh16 = (__half*)(smem + OFF_PH);

        float mxls = fmaxf(ls0, ls1);
        #pragma unroll
        for (int o = 16; o > 0; o >>= 1)
            mxls = fmaxf(mxls, __shfl_xor_sync(0xffffffffu, mxls, o));

        #pragma unroll
        for (int base = 0; base < NROWS; base += 8) {
            float e0[8], e1[8], s[8];
            #pragma unroll
            for (int r = 0; r < 8; r++) {
                const int i = lw + (base + r) * NWU;
                const float ldi = sLD[u * 64 + i];
                float v0 = ldi + ls0;
                float v1 = ldi + ls1;
                v0 = (v0 > 0.f) ? v0 : NEG_SLOPE * v0;
                v1 = (v1 > 0.f) ? v1 : NEG_SLOPE * v1;
                float mr2 = ldi + mxls;
                mr2 = (mr2 > 0.f) ? mr2 : NEG_SLOPE * mr2;
                e0[r] = __expf(v0 - mr2);
                e1[r] = __expf(v1 - mr2);
                s[r] = e0[r] + e1[r];
            }
            #pragma unroll
            for (int o = 16; o > 0; o >>= 1)
                #pragma unroll
                for (int r = 0; r < 8; r++)
                    s[r] += __shfl_xor_sync(0xffffffffu, s[r], o);
            #pragma unroll
            for (int r = 0; r < 8; r++) {
                const int i = lw + (base + r) * NWU;
                const float inv = 1.f / s[r];
                const int base16 = (u * 64 + i) * 72;
                sPh16[base16 + lane]      = __float2half(e0[r] * inv);
                sPh16[base16 + lane + 32] = __float2half(e1[r] * inv);
            }
        }
    }
    __syncthreads();

    {
        const int uw = wid & 1;
        const int m0 = uw * 32;
        const uint32_t sH_a  = smem_base + OFF_SH;
        const uint32_t sPh_a = smem_base + OFF_PH + u * 9216;

        float oa[2][4][4];
        #pragma unroll
        for (int mt = 0; mt < 2; mt++)
            #pragma unroll
            for (int nt = 0; nt < 4; nt++)
                #pragma unroll
                for (int q = 0; q < 4; q++) oa[mt][nt][q] = 0.f;

        #pragma unroll
        for (int kt = 0; kt < 4; kt++) {
            uint32_t fbk[2][4];
            #pragma unroll
            for (int ng = 0; ng < 2; ng++) {
                int br = sbu * 64 + kt * 16 + rowlA;
                int bc = cb + ng * 16 + chA * 8;
                ldsm4t(fbk[ng], sH_a + (uint32_t)((br * 72 + bc) << 1));
            }
            #pragma unroll
            for (int mt = 0; mt < 2; mt++) {
                uint32_t ah[4];
                uint32_t aoff = (uint32_t)(((m0 + mt * 16 + rowlA) * 72
                                            + kt * 16 + chA * 8) << 1);
                ldsm4(ah, sPh_a + aoff);
                #pragma unroll
                for (int nt = 0; nt < 4; nt++) {
                    const uint32_t bb[2] = {fbk[nt >> 1][(nt & 1) * 2],
                                            fbk[nt >> 1][(nt & 1) * 2 + 1]};
                    mma16816(oa[mt][nt], ah, bb);
                }
            }
        }
        __syncthreads();

        float* sO = (float*)(smem + OFF_PH);   // [4][64][33]
        {
            const int gid = lane >> 2;
            const int tig = lane & 3;
            #pragma unroll
            for (int mt = 0; mt < 2; mt++) {
                #pragma unroll
                for (int nt = 0; nt < 4; nt++) {
                    int r = m0 + mt * 16 + gid;
                    int c = nt * 8 + tig * 2;
                    float b0f = sBI[cb + c], b1f = sBI[cb + c + 1];
                    sO[(u * 64 + r) * 33 + c]         = oa[mt][nt][0] + b0f;
                    sO[(u * 64 + r) * 33 + c + 1]     = oa[mt][nt][1] + b1f;
                    sO[(u * 64 + r + 8) * 33 + c]     = oa[mt][nt][2] + b0f;
                    sO[(u * 64 + r + 8) * 33 + c + 1] = oa[mt][nt][3] + b1f;
                }
            }
        }
        __syncthreads();
        if (ut < 32) {
            const int c = ut;
            float s = 0.f;
            #pragma unroll 8
            for (int n = 0; n < 64; n++)
                s += sO[(u * 64 + n) * 33 + c];
            const int g  = blockIdx.y * 2 + sbu;
            const int hd = blockIdx.x * HPT + hl;
            outmean[(size_t)g * HC3 + hd * 32 + c] = s * (1.0f / 64.f);
        }
    }
}

// ---------------------------------------------------------------------
extern "C" void kernel_launch(void* const* d_in, const int* in_sizes, int n_in,
                              void* d_out, int out_size) {
    const float* xs      = (const float*)d_in[0];
    const float* pos_enc = (const float*)d_in[1];
    const float* W1  = (const float*)d_in[2];
    const float* as1 = (const float*)d_in[3];
    const float* ad1 = (const float*)d_in[4];
    const float* b1  = (const float*)d_in[5];
    const float* W2  = (const float*)d_in[6];
    const float* as2 = (const float*)d_in[7];
    const float* ad2 = (const float*)d_in[8];
    const float* b2  = (const float*)d_in[9];
    const float* W3  = (const float*)d_in[10];
    const float* as3 = (const float*)d_in[11];
    const float* ad3 = (const float*)d_in[12];
    const float* b3  = (const float*)d_in[13];
    float* out = (float*)d_out;

    __half *a0, *a1, *a2, *w1, *w2, *w3;
    cudaGetSymbolAddress((void**)&a0, g_a0);
    cudaGetSymbolAddress((void**)&a1, g_a1);
    cudaGetSymbolAddress((void**)&a2, g_a2);
    cudaGetSymbolAddress((void**)&w1, g_w1);
    cudaGetSymbolAddress((void**)&w2, g_w2);
    cudaGetSymbolAddress((void**)&w3, g_w3);

    const int SMEW = 86016 + 2048 + 1536;                  // 89600
    const int SME0 = 92160 + 2 * (4 * 64 * 4) + 3 * 256;   // 94976
    cudaFuncSetAttribute(gemm_attn_wide<64>,
        cudaFuncAttributeMaxDynamicSharedMemorySize, SMEW);
    cudaFuncSetAttribute(gemm_attn_wide<512>,
        cudaFuncAttributeMaxDynamicSharedMemorySize, SMEW);
    cudaFuncSetAttribute(gemm_attn_l3<512, 32>,
        cudaFuncAttributeMaxDynamicSharedMemorySize, SME0);

    // prep
    build_x0_h<<<(MROWS * 64 + 255) / 256, 256>>>(xs, pos_enc, a0);
    {
        int total = 32768 + 262144 + 131072;
        prep_w_all<<<(total + 255) / 256, 256>>>(W1, W2, W3, w1, w2, w3);
    }

    // layer 1
    gemm_attn_wide<64><<<dim3(HC12 / 128, MROWS / 128), 256, SMEW>>>(
        a0, w1, as1, ad1, b1, a1);
    // layer 2
    gemm_attn_wide<512><<<dim3(HC12 / 128, MROWS / 128), 256, SMEW>>>(
        a1, w2, as2, ad2, b2, a2);
    // layer 3
    gemm_attn_l3<512, 32><<<dim3(HC3 / 64, MROWS / 128), 256, SME0>>>(
        a2, w3, as3, ad3, b3, out);
}

// round 17
// speedup vs baseline: 1.0030x; 1.0030x over previous
#include <cuda_runtime.h>
#include <cuda_fp16.h>
#include <cstdint>

// Problem constants
#define BS        8
#define RDIM      256
#define NBLK      (BS * RDIM)      // 2048
#define NODES     64
#define MROWS     (NBLK * NODES)   // 131072
#define ENC       31
#define FIN       32
#define HEADS     8
#define HID       64
#define OUTC      32
#define HC12      (HEADS * HID)    // 512
#define HC3       (HEADS * OUTC)   // 256
#define NEG_SLOPE 0.2f

__device__ __forceinline__ uint32_t smem_u32(const void* p) {
    uint32_t a;
    asm("{ .reg .u64 t; cvta.to.shared.u64 t, %1; cvt.u32.u64 %0, t; }" : "=r"(a) : "l"(p));
    return a;
}

// ---------------- mma.sync / ldmatrix / cp.async ----------------
__device__ __forceinline__ void ldsm4(uint32_t* r, uint32_t addr) {
    asm volatile("ldmatrix.sync.aligned.m8n8.x4.shared.b16 {%0,%1,%2,%3}, [%4];"
        : "=r"(r[0]), "=r"(r[1]), "=r"(r[2]), "=r"(r[3]) : "r"(addr));
}
__device__ __forceinline__ void ldsm4t(uint32_t* r, uint32_t addr) {
    asm volatile("ldmatrix.sync.aligned.m8n8.x4.trans.shared.b16 {%0,%1,%2,%3}, [%4];"
        : "=r"(r[0]), "=r"(r[1]), "=r"(r[2]), "=r"(r[3]) : "r"(addr));
}
__device__ __forceinline__ void mma16816(float* d, const uint32_t* a, const uint32_t* b) {
    asm volatile(
        "mma.sync.aligned.m16n8k16.row.col.f32.f16.f16.f32 "
        "{%0,%1,%2,%3}, {%4,%5,%6,%7}, {%8,%9}, {%0,%1,%2,%3};"
        : "+f"(d[0]), "+f"(d[1]), "+f"(d[2]), "+f"(d[3])
        : "r"(a[0]), "r"(a[1]), "r"(a[2]), "r"(a[3]), "r"(b[0]), "r"(b[1]));
}
__device__ __forceinline__ void cp16(uint32_t dst, const void* src) {
    asm volatile("cp.async.cg.shared.global [%0], [%1], 16;" :: "r"(dst), "l"(src));
}
#define CP_COMMIT() asm volatile("cp.async.commit_group;" ::: "memory")
#define CP_WAIT(n)  asm volatile("cp.async.wait_group %0;" :: "n"(n) : "memory")

// ---------------- device scratch ----------------
__device__ __half g_a0[(size_t)MROWS * 64];
__device__ __half g_a1[(size_t)MROWS * HC12];
__device__ __half g_a2[(size_t)MROWS * HC12];
__device__ __half g_w1[512 * 64];
__device__ __half g_w2[512 * 512];
__device__ __half g_w3[256 * 512];

// ---------------- prep kernels ----------------
__global__ void build_x0_h(const float* __restrict__ xs,
                           const float* __restrict__ pos_enc,
                           __half* __restrict__ a0) {
    int idx = blockIdx.x * blockDim.x + threadIdx.x;   // MROWS*64
    if (idx >= MROWS * 64) return;
    int m = idx >> 6;
    int f = idx & 63;
    float v = 0.f;
    if (f == 0) v = xs[m];
    else if (f < FIN) {
        int b = m / (RDIM * NODES);
        int n = m % NODES;
        v = pos_enc[(b * NODES + n) * ENC + (f - 1)];
    }
    a0[idx] = __float2half(v);
}

// All three weight transposes in one launch.
// w1: N=512,Kpad=64,Ksrc=32 (32768) | w2: 512,512,512 (262144) | w3: 256,512,512 (131072)
__global__ void prep_w_all(const float* __restrict__ W1f,
                           const float* __restrict__ W2f,
                           const float* __restrict__ W3f,
                           __half* __restrict__ w1, __half* __restrict__ w2,
                           __half* __restrict__ w3) {
    int idx = blockIdx.x * blockDim.x + threadIdx.x;
    if (idx < 32768) {
        int n = idx >> 6, k = idx & 63;
        float v = (k < FIN) ? W1f[(size_t)k * 512 + n] : 0.f;
        w1[idx] = __float2half(v);
    } else if (idx < 32768 + 262144) {
        int j = idx - 32768;
        int n = j >> 9, k = j & 511;
        w2[j] = __float2half(W2f[(size_t)k * 512 + n]);
    } else if (idx < 32768 + 262144 + 131072) {
        int j = idx - 32768 - 262144;
        int n = j >> 9, k = j & 511;
        w3[j] = __float2half(W3f[(size_t)k * 256 + n]);
    }
}

#define STS_OFF(row, c) ((row) * 64 + ((((c) ^ (((row) >> 1) & 3))) << 4))

// =====================================================================
// WIDE kernel (layers 1-2): tile 128 rows x 128 cols (2 blocks x 2 heads).
// 3-stage cp.async; H fp16 ALIASES the stage region (dead after mainloop);
// ls/ld from accumulators; P hi-only fp16; TC AV; staged store.
// smem: [0,49152) stages / H fp16 [128][136] (alias)
//       [49152, 86016) P hi fp16 [4][64][72]
//       [86016, ...)   sLS/sLD [4][64], sAS/sAD/sBI [128]
// =====================================================================
#define WSTAGE 16384   // A 8KB @0 | B 8KB @8192

template<int K>
__global__ __launch_bounds__(256, 2) void gemm_attn_wide(
    const __half* __restrict__ A, const __half* __restrict__ B,
    const float* __restrict__ a_src, const float* __restrict__ a_dst,
    const float* __restrict__ bias, __half* __restrict__ oact) {
    constexpr int T = K / 32;
    constexpr int OFF_SH   = 0;                  // aliases stage region (49152)
    constexpr int OFF_PH   = 49152;              // P hi fp16 [4][64][72] = 36864
    constexpr int OFF_TAIL = 86016;

    extern __shared__ __align__(16) char smem[];
    float* sLS = (float*)(smem + OFF_TAIL);      // [4][64]
    float* sLD = sLS + 256;                      // [4][64]
    float* sAS = sLD + 256;                      // [128]
    float* sAD = sAS + 128;
    float* sBI = sAD + 128;
    __half* sH = (__half*)(smem + OFF_SH);
    __half* Ph = (__half*)(smem + OFF_PH);

    const int tid  = threadIdx.x;
    const int wid  = tid >> 5;
    const int lane = tid & 31;
    const int gid  = lane >> 2;
    const int tig  = lane & 3;
    const int row0 = blockIdx.y * 128;
    const int col0 = blockIdx.x * 128;
    const uint32_t smem_base = smem_u32(smem);

    // preload attention params; zero ls/ld reducers
    if (tid < 128) {
        sAS[tid] = a_src[col0 + tid];
        sAD[tid] = a_dst[col0 + tid];
        sBI[tid] = bias[col0 + tid];
    }
    sLS[tid] = 0.f;
    sLD[tid] = 0.f;

    // ---- GEMM global->smem mapping ----
    const int arow = tid >> 1;                   // 0..127
    const int ac2  = (tid & 1) * 2;              // chunk 0/2
    const uint32_t sA0 = STS_OFF(arow, ac2);
    const uint32_t sA1 = STS_OFF(arow, ac2 + 1);
    const __half* gA = A + (size_t)(row0 + arow) * K + ac2 * 8;
    const __half* gB = B + (size_t)(col0 + arow) * K + ac2 * 8;

    const int mr = (wid & 1) * 64;               // warp rows (4 m-tiles)
    const int nb = (wid >> 1) * 32;              // warp cols (4 n8-tiles)
    const int rowlA = (lane & 7) + ((lane >> 3) & 1) * 8;
    const int chA   = lane >> 4;
    const int rowlB = (lane & 7) + (lane >> 4) * 8;
    const int chB   = (lane >> 3) & 1;

    float acc[4][4][4];
    #pragma unroll
    for (int i = 0; i < 4; i++)
        #pragma unroll
        for (int j = 0; j < 4; j++)
            #pragma unroll
            for (int q = 0; q < 4; q++) acc[i][j][q] = 0.f;

    auto issue = [&](int s, int k0) {
        const uint32_t sb = smem_base + s * WSTAGE;
        cp16(sb + sA0, gA + k0);
        cp16(sb + sA1, gA + k0 + 8);
        cp16(sb + 8192 + sA0, gB + k0);
        cp16(sb + 8192 + sA1, gB + k0 + 8);
    };

    // 3-stage prologue
    issue(0, 0);
    CP_COMMIT();
    if (T > 1) { issue(1, 32); CP_COMMIT(); }

    int buf = 0;
    #pragma unroll 1
    for (int t = 0; t < T; t++) {
        if (t + 1 < T) { CP_WAIT(1); } else { CP_WAIT(0); }
        __syncthreads();
        if (t + 2 < T) {
            int nx = buf + 2; if (nx >= 3) nx -= 3;
            issue(nx, (t + 2) * 32);             // overlaps compute below
            CP_COMMIT();
        }
        const uint32_t stg = smem_base + buf * WSTAGE;
        #pragma unroll
        for (int kk = 0; kk < 2; kk++) {
            const int c0 = kk * 2;
            uint32_t fA[4][4], fB[2][4];
            #pragma unroll
            for (int mt = 0; mt < 4; mt++) {
                int r = mr + mt * 16 + rowlA;
                uint32_t off = r * 64 + (((c0 + chA) ^ ((r >> 1) & 3)) << 4);
                ldsm4(fA[mt], stg + off);
            }
            #pragma unroll
            for (int tp = 0; tp < 2; tp++) {
                int r = nb + tp * 16 + rowlB;
                uint32_t off = r * 64 + (((c0 + chB) ^ ((r >> 1) & 3)) << 4);
                ldsm4(fB[tp], stg + 8192 + off);
            }
            #pragma unroll
            for (int mt = 0; mt < 4; mt++)
                #pragma unroll
                for (int tn = 0; tn < 4; tn++) {
                    const int tp = tn >> 1, hf = (tn & 1) * 2;
                    const uint32_t bb[2] = {fB[tp][hf], fB[tp][hf + 1]};
                    mma16816(acc[mt][tn], fA[mt], bb);
                }
        }
        if (++buf == 3) buf = 0;
    }
    __syncthreads();   // all stage reads done — safe to overwrite with sH

    // ---- epilogue: acc -> sH fp16 (aliased); ls/ld partials from acc ----
    {
        #pragma unroll
        for (int mt = 0; mt < 4; mt++)
            #pragma unroll
            for (int tn = 0; tn < 4; tn++) {
                int r = mr + mt * 16 + gid;
                int c = nb + tn * 8 + tig * 2;
                *(__half2*)&sH[r * 136 + c] =
                    __floats2half2_rn(acc[mt][tn][0], acc[mt][tn][1]);
                *(__half2*)&sH[(r + 8) * 136 + c] =
                    __floats2half2_rn(acc[mt][tn][2], acc[mt][tn][3]);
            }

        float lsp[8], ldp[8];
        #pragma unroll
        for (int i = 0; i < 8; i++) { lsp[i] = 0.f; ldp[i] = 0.f; }
        #pragma unroll
        for (int mt = 0; mt < 4; mt++)
            #pragma unroll
            for (int h = 0; h < 2; h++) {
                const int i = mt * 2 + h;
                #pragma unroll
                for (int tn = 0; tn < 4; tn++)
                    #pragma unroll
                    for (int e = 0; e < 2; e++) {
                        int c = nb + tn * 8 + tig * 2 + e;
                        float a = acc[mt][tn][h * 2 + e];
                        lsp[i] += a * sAS[c];
                        ldp[i] += a * sAD[c];
                    }
            }
        #pragma unroll
        for (int i = 0; i < 8; i++) {
            lsp[i] += __shfl_down_sync(0xffffffffu, lsp[i], 2, 4);
            lsp[i] += __shfl_down_sync(0xffffffffu, lsp[i], 1, 4);
            ldp[i] += __shfl_down_sync(0xffffffffu, ldp[i], 2, 4);
            ldp[i] += __shfl_down_sync(0xffffffffu, ldp[i], 1, 4);
        }
        if (tig == 0) {
            #pragma unroll
            for (int i = 0; i < 8; i++) {
                int ar = mr + (i >> 1) * 16 + gid + (i & 1) * 8;
                int u  = ((ar >> 6) << 1) + (nb >> 6);
                atomicAdd(&sLS[u * 64 + (ar & 63)], lsp[i]);
                atomicAdd(&sLD[u * 64 + (ar & 63)], ldp[i]);
            }
        }
    }
    __syncthreads();

    // ---- softmax: U=4 units, 2 warps each; hi-only fp16 P ----
    {
        const int u  = tid >> 6;
        const int ut = tid & 63;
        const int lw = ut >> 5;
        const float ls0 = sLS[u * 64 + lane];
        const float ls1 = sLS[u * 64 + lane + 32];
        float mxls = fmaxf(ls0, ls1);
        #pragma unroll
        for (int o = 16; o > 0; o >>= 1)
            mxls = fmaxf(mxls, __shfl_xor_sync(0xffffffffu, mxls, o));

        #pragma unroll
        for (int base = 0; base < 32; base += 8) {
            float e0[8], e1[8], s[8];
            #pragma unroll
            for (int r = 0; r < 8; r++) {
                const int i = lw + (base + r) * 2;
                const float ldi = sLD[u * 64 + i];
                float v0 = ldi + ls0;
                float v1 = ldi + ls1;
                v0 = (v0 > 0.f) ? v0 : NEG_SLOPE * v0;
                v1 = (v1 > 0.f) ? v1 : NEG_SLOPE * v1;
                float mr2 = ldi + mxls;        // exact row max (lrelu monotone)
                mr2 = (mr2 > 0.f) ? mr2 : NEG_SLOPE * mr2;
                e0[r] = __expf(v0 - mr2);
                e1[r] = __expf(v1 - mr2);
                s[r] = e0[r] + e1[r];
            }
            #pragma unroll
            for (int o = 16; o > 0; o >>= 1)
                #pragma unroll
                for (int r = 0; r < 8; r++)
                    s[r] += __shfl_xor_sync(0xffffffffu, s[r], o);
            #pragma unroll
            for (int r = 0; r < 8; r++) {
                const int i = lw + (base + r) * 2;
                const float inv = 1.f / s[r];
                Ph[(u * 64 + i) * 72 + lane]      = __float2half(e0[r] * inv);
                Ph[(u * 64 + i) * 72 + lane + 32] = __float2half(e1[r] * inv);
            }
        }
    }
    __syncthreads();

    // ---- AV via tensor cores: per unit out[64x64] = P @ H_unit ----
    {
        const int uu  = wid >> 1;            // unit 0..3
        const int uw  = wid & 1;             // warp within unit
        const int sbu = uu >> 1;             // block half
        const int cb  = (uu & 1) * 64;       // head col offset
        const int m0  = uw * 32;
        const uint32_t Ph_a = smem_base + OFF_PH + uu * 9216;
        const uint32_t sH_a = smem_base + OFF_SH;

        float oa[2][8][4];
        #pragma unroll
        for (int mt = 0; mt < 2; mt++)
            #pragma unroll
            for (int nt = 0; nt < 8; nt++)
                #pragma unroll
                for (int q = 0; q < 4; q++) oa[mt][nt][q] = 0.f;

        #pragma unroll
        for (int kt = 0; kt < 4; kt++) {
            uint32_t ah[2][4];
            #pragma unroll
            for (int mt = 0; mt < 2; mt++)
                ldsm4(ah[mt], Ph_a +
                    (uint32_t)(((m0 + mt * 16 + rowlA) * 72 + kt * 16 + chA * 8) << 1));
            uint32_t fb[4][4];
            #pragma unroll
            for (int ng = 0; ng < 4; ng++) {
                int br = sbu * 64 + kt * 16 + rowlA;
                int bc = cb + ng * 16 + chA * 8;
                ldsm4t(fb[ng], sH_a + (uint32_t)((br * 136 + bc) << 1));
            }
            #pragma unroll
            for (int mt = 0; mt < 2; mt++)
                #pragma unroll
                for (int nt = 0; nt < 8; nt++) {
                    const int ng = nt >> 1, hf = (nt & 1) * 2;
                    const uint32_t bb[2] = {fb[ng][hf], fb[ng][hf + 1]};
                    mma16816(oa[mt][nt], ah[mt], bb);
                }
        }
        __syncthreads();                     // all P/H reads done before overwrite

        // fragments + bias -> sH fp16 (overwrite)
        #pragma unroll
        for (int mt = 0; mt < 2; mt++)
            #pragma unroll
            for (int nt = 0; nt < 8; nt++) {
                int r = sbu * 64 + m0 + mt * 16 + gid;
                int c = cb + nt * 8 + tig * 2;
                float b0f = sBI[c], b1f = sBI[c + 1];
                *(__half2*)&sH[r * 136 + c] =
                    __floats2half2_rn(oa[mt][nt][0] + b0f, oa[mt][nt][1] + b1f);
                *(__half2*)&sH[(r + 8) * 136 + c] =
                    __floats2half2_rn(oa[mt][nt][2] + b0f, oa[mt][nt][3] + b1f);
            }
    }
    __syncthreads();

    // ---- coalesced global store: 2 threads/row, 64 cols each ----
    {
        const int rr = tid >> 1;
        const int hh = tid & 1;
        const uint4* src = (const uint4*)(sH + rr * 136 + hh * 64);
        __half* dst = oact + (size_t)(row0 + rr) * HC12 + col0 + hh * 64;
        #pragma unroll
        for (int k = 0; k < 8; k++)
            *(uint4*)(dst + k * 8) = src[k];
    }
}

// =====================================================================
// Layer-3 kernel: unchanged proven path (tile 128x64, TC AV, mean).
// =====================================================================
#define STAGE 12288

template<int K, int CH>
__global__ __launch_bounds__(256, 2) void gemm_attn_l3(
    const __half* __restrict__ A, const __half* __restrict__ B,
    const float* __restrict__ a_src, const float* __restrict__ a_dst,
    const float* __restrict__ bias, float* __restrict__ outmean) {
    constexpr int HPT = 64 / CH;     // 2
    constexpr int U   = 2 * HPT;     // 4
    constexpr int TU  = 256 / U;     // 64
    constexpr int T   = K / 32;
    constexpr int OFF_SH   = 36864;
    constexpr int OFF_PH   = OFF_SH + 18432;
    constexpr int OFF_TAIL = 92160;

    extern __shared__ __align__(16) char smem[];
    float* sC  = (float*)smem;                   // [128][68] fp32 (aliases stages)
    float* sLS = (float*)(smem + OFF_TAIL);
    float* sLD = sLS + U * 64;
    float* sAS = sLD + U * 64;
    float* sAD = sAS + 64;
    float* sBI = sAD + 64;

    const int tid  = threadIdx.x;
    const int wid  = tid >> 5;
    const int lane = tid & 31;
    const int row0 = blockIdx.y * 128;
    const int col0 = blockIdx.x * 64;
    const uint32_t smem_base = smem_u32(smem);

    const int arow0 = tid >> 2;
    const int ac    = tid & 3;
    const uint32_t a_sts0 = STS_OFF(arow0, ac);
    const uint32_t a_sts1 = STS_OFF(arow0 + 64, ac);
    const uint32_t b_sts  = STS_OFF(arow0, ac);

    const __half* gA0 = A + (size_t)(row0 + arow0) * K + ac * 8;
    const __half* gA1 = gA0 + (size_t)64 * K;
    const __half* gB  = B + (size_t)(col0 + arow0) * K + ac * 8;

    const int mr = (wid & 3) * 32;
    const int nb = (wid >> 2) * 32;
    const int rowlA = (lane & 7) + ((lane >> 3) & 1) * 8;
    const int chA   = (lane >> 4);
    const int rowlB = (lane & 7) + (lane >> 4) * 8;
    const int chB   = (lane >> 3) & 1;

    float acc[2][4][4];
    #pragma unroll
    for (int i = 0; i < 2; i++)
        #pragma unroll
        for (int j = 0; j < 4; j++)
            #pragma unroll
            for (int q = 0; q < 4; q++) acc[i][j][q] = 0.f;

    auto issue_stage = [&](int s, int k0) {
        const uint32_t sb = smem_base + s * STAGE;
        cp16(sb + a_sts0, gA0 + k0);
        cp16(sb + a_sts1, gA1 + k0);
        cp16(sb + 8192 + b_sts, gB + k0);
    };

    issue_stage(0, 0);
    CP_COMMIT();
    if (T > 1) { issue_stage(1, 32); CP_COMMIT(); }

    int buf = 0;
    #pragma unroll 1
    for (int t = 0; t < T; t++) {
        if (t + 1 < T) { CP_WAIT(1); } else { CP_WAIT(0); }
        __syncthreads();
        if (t + 2 < T) {
            int nb3 = buf + 2; if (nb3 >= 3) nb3 -= 3;
            issue_stage(nb3, (t + 2) * 32);
            CP_COMMIT();
        }
        const uint32_t stg = smem_base + buf * STAGE;
        #pragma unroll
        for (int kk = 0; kk < 2; kk++) {
            const int c0 = kk * 2;
            uint32_t fA[2][4], fB[2][4];
            #pragma unroll
            for (int sm = 0; sm < 2; sm++) {
                int r = mr + sm * 16 + rowlA;
                uint32_t off = r * 64 + (((c0 + chA) ^ ((r >> 1) & 3)) << 4);
                ldsm4(fA[sm], stg + off);
            }
            #pragma unroll
            for (int tp = 0; tp < 2; tp++) {
                int r = nb + tp * 16 + rowlB;
                uint32_t off = r * 64 + (((c0 + chB) ^ ((r >> 1) & 3)) << 4);
                ldsm4(fB[tp], stg + 8192 + off);
            }
            #pragma unroll
            for (int sm = 0; sm < 2; sm++)
                #pragma unroll
                for (int tn = 0; tn < 4; tn++) {
                    const int tp = tn >> 1, hf = (tn & 1) * 2;
                    const uint32_t bb[2] = {fB[tp][hf], fB[tp][hf + 1]};
                    mma16816(acc[sm][tn], fA[sm], bb);
                }
        }
        if (++buf == 3) buf = 0;
    }
    __syncthreads();

    {
        const int gid = lane >> 2;
        const int tig = lane & 3;
        __half* sH = (__half*)(smem + OFF_SH);
        #pragma unroll
        for (int sm = 0; sm < 2; sm++) {
            #pragma unroll
            for (int tn = 0; tn < 4; tn++) {
                int r = mr + sm * 16 + gid;
                int c = nb + tn * 8 + tig * 2;
                *(float2*)&sC[r * 68 + c] = make_float2(acc[sm][tn][0], acc[sm][tn][1]);
                *(float2*)&sC[(r + 8) * 68 + c] = make_float2(acc[sm][tn][2], acc[sm][tn][3]);
                *(__half2*)&sH[r * 72 + c] =
                    __floats2half2_rn(acc[sm][tn][0], acc[sm][tn][1]);
                *(__half2*)&sH[(r + 8) * 72 + c] =
                    __floats2half2_rn(acc[sm][tn][2], acc[sm][tn][3]);
            }
        }
    }
    if (tid < 64) {
        sAS[tid] = a_src[col0 + tid];
        sAD[tid] = a_dst[col0 + tid];
        sBI[tid] = bias[col0 + tid];
    }
    __syncthreads();

    const int u  = tid / TU;
    const int ut = tid % TU;
    const int sbu = u / HPT;
    const int hl  = u % HPT;
    const int cb  = hl * CH;

    if (ut < 64) {
        const int n = ut;
        const float* hp = &sC[(sbu * 64 + n) * 68 + cb];
        float ls = 0.f, ld = 0.f;
        #pragma unroll
        for (int c = 0; c < CH; c++) {
            float hv = hp[c];
            ls += hv * sAS[cb + c];
            ld += hv * sAD[cb + c];
        }
        sLS[u * 64 + n] = ls;
        sLD[u * 64 + n] = ld;
    }
    __syncthreads();

    {
        constexpr int NWU   = TU / 32;
        constexpr int NROWS = 64 / NWU;
        const int lw = ut >> 5;
        const float ls0 = sLS[u * 64 + lane];
        const float ls1 = sLS[u * 64 + lane + 32];
        __half* sPh16 = (__half*)(smem + OFF_PH);

        float mxls = fmaxf(ls0, ls1);
        #pragma unroll
        for (int o = 16; o > 0; o >>= 1)
            mxls = fmaxf(mxls, __shfl_xor_sync(0xffffffffu, mxls, o));

        #pragma unroll
        for (int base = 0; base < NROWS; base += 8) {
            float e0[8], e1[8], s[8];
            #pragma unroll
            for (int r = 0; r < 8; r++) {
                const int i = lw + (base + r) * NWU;
                const float ldi = sLD[u * 64 + i];
                float v0 = ldi + ls0;
                float v1 = ldi + ls1;
                v0 = (v0 > 0.f) ? v0 : NEG_SLOPE * v0;
                v1 = (v1 > 0.f) ? v1 : NEG_SLOPE * v1;
                float mr2 = ldi + mxls;
                mr2 = (mr2 > 0.f) ? mr2 : NEG_SLOPE * mr2;
                e0[r] = __expf(v0 - mr2);
                e1[r] = __expf(v1 - mr2);
                s[r] = e0[r] + e1[r];
            }
            #pragma unroll
            for (int o = 16; o > 0; o >>= 1)
                #pragma unroll
                for (int r = 0; r < 8; r++)
                    s[r] += __shfl_xor_sync(0xffffffffu, s[r], o);
            #pragma unroll
            for (int r = 0; r < 8; r++) {
                const int i = lw + (base + r) * NWU;
                const float inv = 1.f / s[r];
                const int base16 = (u * 64 + i) * 72;
                sPh16[base16 + lane]      = __float2half(e0[r] * inv);
                sPh16[base16 + lane + 32] = __float2half(e1[r] * inv);
            }
        }
    }
    __syncthreads();

    {
        const int uw = wid & 1;
        const int m0 = uw * 32;
        const uint32_t sH_a  = smem_base + OFF_SH;
        const uint32_t sPh_a = smem_base + OFF_PH + u * 9216;

        float oa[2][4][4];
        #pragma unroll
        for (int mt = 0; mt < 2; mt++)
            #pragma unroll
            for (int nt = 0; nt < 4; nt++)
                #pragma unroll
                for (int q = 0; q < 4; q++) oa[mt][nt][q] = 0.f;

        #pragma unroll
        for (int kt = 0; kt < 4; kt++) {
            uint32_t fbk[2][4];
            #pragma unroll
            for (int ng = 0; ng < 2; ng++) {
                int br = sbu * 64 + kt * 16 + rowlA;
                int bc = cb + ng * 16 + chA * 8;
                ldsm4t(fbk[ng], sH_a + (uint32_t)((br * 72 + bc) << 1));
            }
            #pragma unroll
            for (int mt = 0; mt < 2; mt++) {
                uint32_t ah[4];
                uint32_t aoff = (uint32_t)(((m0 + mt * 16 + rowlA) * 72
                                            + kt * 16 + chA * 8) << 1);
                ldsm4(ah, sPh_a + aoff);
                #pragma unroll
                for (int nt = 0; nt < 4; nt++) {
                    const uint32_t bb[2] = {fbk[nt >> 1][(nt & 1) * 2],
                                            fbk[nt >> 1][(nt & 1) * 2 + 1]};
                    mma16816(oa[mt][nt], ah, bb);
                }
            }
        }
        __syncthreads();

        float* sO = (float*)(smem + OFF_PH);   // [4][64][33]
        {
            const int gid = lane >> 2;
            const int tig = lane & 3;
            #pragma unroll
            for (int mt = 0; mt < 2; mt++) {
                #pragma unroll
                for (int nt = 0; nt < 4; nt++) {
                    int r = m0 + mt * 16 + gid;
                    int c = nt * 8 + tig * 2;
                    float b0f = sBI[cb + c], b1f = sBI[cb + c + 1];
                    sO[(u * 64 + r) * 33 + c]         = oa[mt][nt][0] + b0f;
                    sO[(u * 64 + r) * 33 + c + 1]     = oa[mt][nt][1] + b1f;
                    sO[(u * 64 + r + 8) * 33 + c]     = oa[mt][nt][2] + b0f;
                    sO[(u * 64 + r + 8) * 33 + c + 1] = oa[mt][nt][3] + b1f;
                }
            }
        }
        __syncthreads();
        if (ut < 32) {
            const int c = ut;
            float s = 0.f;
            #pragma unroll 8
            for (int n = 0; n < 64; n++)
                s += sO[(u * 64 + n) * 33 + c];
            const int g  = blockIdx.y * 2 + sbu;
            const int hd = blockIdx.x * HPT + hl;
            outmean[(size_t)g * HC3 + hd * 32 + c] = s * (1.0f / 64.f);
        }
    }
}

// ---------------------------------------------------------------------
extern "C" void kernel_launch(void* const* d_in, const int* in_sizes, int n_in,
                              void* d_out, int out_size) {
    const float* xs      = (const float*)d_in[0];
    const float* pos_enc = (const float*)d_in[1];
    const float* W1  = (const float*)d_in[2];
    const float* as1 = (const float*)d_in[3];
    const float* ad1 = (const float*)d_in[4];
    const float* b1  = (const float*)d_in[5];
    const float* W2  = (const float*)d_in[6];
    const float* as2 = (const float*)d_in[7];
    const float* ad2 = (const float*)d_in[8];
    const float* b2  = (const float*)d_in[9];
    const float* W3  = (const float*)d_in[10];
    const float* as3 = (const float*)d_in[11];
    const float* ad3 = (const float*)d_in[12];
    const float* b3  = (const float*)d_in[13];
    float* out = (float*)d_out;

    __half *a0, *a1, *a2, *w1, *w2, *w3;
    cudaGetSymbolAddress((void**)&a0, g_a0);
    cudaGetSymbolAddress((void**)&a1, g_a1);
    cudaGetSymbolAddress((void**)&a2, g_a2);
    cudaGetSymbolAddress((void**)&w1, g_w1);
    cudaGetSymbolAddress((void**)&w2, g_w2);
    cudaGetSymbolAddress((void**)&w3, g_w3);

    const int SMEW = 86016 + 2048 + 1536;                  // 89600
    const int SME0 = 92160 + 2 * (4 * 64 * 4) + 3 * 256;   // 94976
    cudaFuncSetAttribute(gemm_attn_wide<64>,
        cudaFuncAttributeMaxDynamicSharedMemorySize, SMEW);
    cudaFuncSetAttribute(gemm_attn_wide<512>,
        cudaFuncAttributeMaxDynamicSharedMemorySize, SMEW);
    cudaFuncSetAttribute(gemm_attn_l3<512, 32>,
        cudaFuncAttributeMaxDynamicSharedMemorySize, SME0);

    // prep
    build_x0_h<<<(MROWS * 64 + 255) / 256, 256>>>(xs, pos_enc, a0);
    {
        int total = 32768 + 262144 + 131072;
        prep_w_all<<<(total + 255) / 256, 256>>>(W1, W2, W3, w1, w2, w3);
    }

    // layer 1
    gemm_attn_wide<64><<<dim3(HC12 / 128, MROWS / 128), 256, SMEW>>>(
        a0, w1, as1, ad1, b1, a1);
    // layer 2
    gemm_attn_wide<512><<<dim3(HC12 / 128, MROWS / 128), 256, SMEW>>>(
        a1, w2, as2, ad2, b2, a2);
    // layer 3
    gemm_attn_l3<512, 32><<<dim3(HC3 / 64, MROWS / 128), 256, SME0>>>(
        a2, w3, as3, ad3, b3, out);
}